// round 1
// baseline (speedup 1.0000x reference)
#include <cuda_runtime.h>
#include <cuda_bf16.h>
#include <cstdint>

#define B_DIM 64
#define H_DIM 512
#define I_DIM 512
#define T_DIM 512
#define GRID_R 128

// ---------------- persistent device state (no allocations allowed) ---------
// double-buffered hidden state, stored TRANSPOSED: [buf][k(H)][m(B)]
__device__ float    g_abuf[2][H_DIM][B_DIM];
__device__ unsigned g_bar_count;   // zero-init at module load; returns to 0 each barrier
__device__ unsigned g_bar_epoch;   // monotonic across launches/replays

// ---------------------------------------------------------------------------
// Kernel 1: U[t,b,h] = sum_i X[b,i,t]*Wax[i,h] + bx[h] + ba[h], written into
// d_out (in-place staging for the recurrence).
// Grid: (8 h-tiles, 8 t-tiles, 64 b). 256 threads, 4x4 micro-tile.
// ---------------------------------------------------------------------------
__global__ void __launch_bounds__(256)
precompute_kernel(const float* __restrict__ X,
                  const float* __restrict__ Wax,
                  const float* __restrict__ bx,
                  const float* __restrict__ ba,
                  float* __restrict__ U)
{
    __shared__ float As[16][64];   // [i-chunk][t]
    __shared__ float Bs[16][64];   // [i-chunk][h]

    const int b  = blockIdx.z;
    const int t0 = blockIdx.y * 64;
    const int h0 = blockIdx.x * 64;
    const int tid = threadIdx.x;
    const int tx = tid & 15;       // h micro index (0..15)
    const int ty = tid >> 4;       // t micro index (0..15)

    const float* Xb = X + (size_t)b * I_DIM * T_DIM;

    float acc[4][4];
#pragma unroll
    for (int r = 0; r < 4; r++)
#pragma unroll
        for (int c = 0; c < 4; c++) acc[r][c] = 0.0f;

    const int lr = tid >> 4;   // load row 0..15
    const int lq = tid & 15;   // float4 index 0..15

    for (int i0 = 0; i0 < I_DIM; i0 += 16) {
        const float4* srcA = (const float4*)(Xb + (size_t)(i0 + lr) * T_DIM + t0);
        const float4* srcB = (const float4*)(Wax + (size_t)(i0 + lr) * H_DIM + h0);
        ((float4*)&As[lr][0])[lq] = srcA[lq];
        ((float4*)&Bs[lr][0])[lq] = srcB[lq];
        __syncthreads();
#pragma unroll
        for (int kk = 0; kk < 16; kk++) {
            float4 av = *(const float4*)&As[kk][ty * 4];
            float4 bv = *(const float4*)&Bs[kk][tx * 4];
            acc[0][0] += av.x * bv.x; acc[0][1] += av.x * bv.y;
            acc[0][2] += av.x * bv.z; acc[0][3] += av.x * bv.w;
            acc[1][0] += av.y * bv.x; acc[1][1] += av.y * bv.y;
            acc[1][2] += av.y * bv.z; acc[1][3] += av.y * bv.w;
            acc[2][0] += av.z * bv.x; acc[2][1] += av.z * bv.y;
            acc[2][2] += av.z * bv.z; acc[2][3] += av.z * bv.w;
            acc[3][0] += av.w * bv.x; acc[3][1] += av.w * bv.y;
            acc[3][2] += av.w * bv.z; acc[3][3] += av.w * bv.w;
        }
        __syncthreads();
    }

    float bias[4];
#pragma unroll
    for (int c = 0; c < 4; c++) {
        int h = h0 + tx * 4 + c;
        bias[c] = bx[h] + ba[h];
    }

#pragma unroll
    for (int r = 0; r < 4; r++) {
        int t = t0 + ty * 4 + r;
        float4 v;
        v.x = acc[r][0] + bias[0];
        v.y = acc[r][1] + bias[1];
        v.z = acc[r][2] + bias[2];
        v.w = acc[r][3] + bias[3];
        *(float4*)&U[(size_t)t * (B_DIM * H_DIM) + (size_t)b * H_DIM + h0 + tx * 4] = v;
    }
}

// ---------------------------------------------------------------------------
// Grid barrier: sense-free epoch barrier. Safe across graph replays because
// g_bar_epoch is monotonic and compared relatively; g_bar_count returns to 0.
// ---------------------------------------------------------------------------
__device__ __forceinline__ void gbar(unsigned target)
{
    __syncthreads();
    if (threadIdx.x == 0) {
        __threadfence();
        unsigned old = atomicAdd(&g_bar_count, 1u);
        if (old == GRID_R - 1) {
            g_bar_count = 0;
            __threadfence();
            atomicAdd(&g_bar_epoch, 1u);
        } else {
            while ((int)(*(volatile unsigned*)&g_bar_epoch - target) < 0) {
                __nanosleep(64);
            }
            __threadfence();
        }
    }
    __syncthreads();
}

// ---------------------------------------------------------------------------
// Kernel 2: persistent recurrence. 128 CTAs (co-resident: 1/SM, 88KB smem).
// CTA (mt,nt): output tile m0..m0+31 (batch) x n0..n0+7 (hidden).
// Waa column slice resident in SMEM. Per step: stage a_t slice (L2, __ldcg),
// K-split across 8 warps, SMEM reduce, tanh, write A[t] and next a buffer.
// ---------------------------------------------------------------------------
__global__ void __launch_bounds__(256, 1)
recurrence_kernel(const float* __restrict__ Waa, float* __restrict__ A)
{
    extern __shared__ float smem[];
    float* Ws  = smem;                   // [512][8]   = 16 KB
    float* As  = Ws + 512 * 8;           // [512][32]  = 64 KB
    float* Red = As + 512 * 32;          // [8][32][8] =  8 KB

    const int tid  = threadIdx.x;
    const int w    = tid >> 5;
    const int lane = tid & 31;
    const int bidx = blockIdx.x;
    const int mt = bidx >> 6;            // 0..1
    const int nt = bidx & 63;            // 0..63
    const int m0 = mt * 32;
    const int n0 = nt * 8;

    // Load resident Waa slice: Ws[k][j] = Waa[k][n0+j]
    for (int idx = tid; idx < 512 * 8; idx += 256) {
        int k = idx >> 3, j = idx & 7;
        Ws[idx] = Waa[(size_t)k * H_DIM + n0 + j];
    }

    // Zero a-buffer 0 cooperatively (256 floats per CTA covers 32768)
    ((float*)g_abuf)[bidx * 256 + tid] = 0.0f;

    unsigned e0 = 0;
    if (tid == 0) e0 = *(volatile unsigned*)&g_bar_epoch;  // before first arrive
    unsigned nb = 0;

    gbar(e0 + (++nb));   // zero-init + all CTAs ready

    const int epi_m = tid >> 3;   // 0..31
    const int epi_n = tid & 7;    // 0..7

    for (int t = 0; t < T_DIM; t++) {
        const float* cur = &g_abuf[t & 1][0][0];
        float*       nxt = &g_abuf[(t + 1) & 1][0][0];

        // Stage a_t slice: As[k][m-m0], k=0..511. 4096 float4s? No: 512 rows * 8 float4.
#pragma unroll
        for (int it = 0; it < 16; it++) {
            int flat = it * 256 + tid;       // 0..4095
            int k = flat >> 3, q = flat & 7;
            float4 v = __ldcg((const float4*)(cur + k * B_DIM + m0) + q);
            *((float4*)&As[k * 32] + q) = v;
        }
        __syncthreads();

        // K-split compute: warp w handles k in [w*64, w*64+64)
        float a0 = 0.f, a1 = 0.f, a2 = 0.f, a3 = 0.f;
        float a4 = 0.f, a5 = 0.f, a6 = 0.f, a7 = 0.f;
        const int k0 = w * 64;
#pragma unroll 8
        for (int k = 0; k < 64; k++) {
            float av = As[(k0 + k) * 32 + lane];
            float4 w0 = *(const float4*)&Ws[(k0 + k) * 8];
            float4 w1 = *(const float4*)&Ws[(k0 + k) * 8 + 4];
            a0 += av * w0.x; a1 += av * w0.y; a2 += av * w0.z; a3 += av * w0.w;
            a4 += av * w1.x; a5 += av * w1.y; a6 += av * w1.z; a7 += av * w1.w;
        }
        float4* rp = (float4*)&Red[(w * 32 + lane) * 8];
        rp[0] = make_float4(a0, a1, a2, a3);
        rp[1] = make_float4(a4, a5, a6, a7);
        __syncthreads();

        // Reduce 8 partials + tanh epilogue
        float s = 0.0f;
#pragma unroll
        for (int ww = 0; ww < 8; ww++)
            s += Red[(ww * 32 + epi_m) * 8 + epi_n];

        size_t oidx = (size_t)t * (B_DIM * H_DIM) + (size_t)(m0 + epi_m) * H_DIM + (n0 + epi_n);
        float val = tanhf(A[oidx] + s);     // A currently holds U[t]
        A[oidx] = val;
        nxt[(n0 + epi_n) * B_DIM + m0 + epi_m] = val;

        gbar(e0 + (++nb));
    }
}

// ---------------------------------------------------------------------------
extern "C" void kernel_launch(void* const* d_in, const int* in_sizes, int n_in,
                              void* d_out, int out_size)
{
    const float* X   = (const float*)d_in[0];
    const float* Wax = (const float*)d_in[1];
    const float* Waa = (const float*)d_in[2];
    const float* bx  = (const float*)d_in[3];
    const float* ba  = (const float*)d_in[4];
    float* out = (float*)d_out;

    const int smem_bytes = (512 * 8 + 512 * 32 + 8 * 32 * 8) * 4;  // 90112
    cudaFuncSetAttribute(recurrence_kernel,
                         cudaFuncAttributeMaxDynamicSharedMemorySize, smem_bytes);

    dim3 g1(H_DIM / 64, T_DIM / 64, B_DIM);   // (8, 8, 64)
    precompute_kernel<<<g1, 256>>>(X, Wax, bx, ba, out);
    recurrence_kernel<<<GRID_R, 256, smem_bytes>>>(Waa, out);
}

// round 2
// speedup vs baseline: 1.0291x; 1.0291x over previous
#include <cuda_runtime.h>
#include <cuda_bf16.h>
#include <cstdint>

#define B_DIM 64
#define H_DIM 512
#define I_DIM 512
#define T_DIM 512

// ---------------------------------------------------------------------------
// Kernel 1: U[t,b,h] = sum_i X[b,i,t]*Wax[i,h] + bx[h] + ba[h], written into
// d_out (in-place staging for the recurrence).  (unchanged from R1 — near
// fp32 FFMA roofline)
// ---------------------------------------------------------------------------
__global__ void __launch_bounds__(256)
precompute_kernel(const float* __restrict__ X,
                  const float* __restrict__ Wax,
                  const float* __restrict__ bx,
                  const float* __restrict__ ba,
                  float* __restrict__ U)
{
    __shared__ float As[16][64];   // [i-chunk][t]
    __shared__ float Bs[16][64];   // [i-chunk][h]

    const int b  = blockIdx.z;
    const int t0 = blockIdx.y * 64;
    const int h0 = blockIdx.x * 64;
    const int tid = threadIdx.x;
    const int tx = tid & 15;
    const int ty = tid >> 4;

    const float* Xb = X + (size_t)b * I_DIM * T_DIM;

    float acc[4][4];
#pragma unroll
    for (int r = 0; r < 4; r++)
#pragma unroll
        for (int c = 0; c < 4; c++) acc[r][c] = 0.0f;

    const int lr = tid >> 4;
    const int lq = tid & 15;

    for (int i0 = 0; i0 < I_DIM; i0 += 16) {
        const float4* srcA = (const float4*)(Xb + (size_t)(i0 + lr) * T_DIM + t0);
        const float4* srcB = (const float4*)(Wax + (size_t)(i0 + lr) * H_DIM + h0);
        ((float4*)&As[lr][0])[lq] = srcA[lq];
        ((float4*)&Bs[lr][0])[lq] = srcB[lq];
        __syncthreads();
#pragma unroll
        for (int kk = 0; kk < 16; kk++) {
            float4 av = *(const float4*)&As[kk][ty * 4];
            float4 bv = *(const float4*)&Bs[kk][tx * 4];
            acc[0][0] += av.x * bv.x; acc[0][1] += av.x * bv.y;
            acc[0][2] += av.x * bv.z; acc[0][3] += av.x * bv.w;
            acc[1][0] += av.y * bv.x; acc[1][1] += av.y * bv.y;
            acc[1][2] += av.y * bv.z; acc[1][3] += av.y * bv.w;
            acc[2][0] += av.z * bv.x; acc[2][1] += av.z * bv.y;
            acc[2][2] += av.z * bv.z; acc[2][3] += av.z * bv.w;
            acc[3][0] += av.w * bv.x; acc[3][1] += av.w * bv.y;
            acc[3][2] += av.w * bv.z; acc[3][3] += av.w * bv.w;
        }
        __syncthreads();
    }

    float bias[4];
#pragma unroll
    for (int c = 0; c < 4; c++) {
        int h = h0 + tx * 4 + c;
        bias[c] = bx[h] + ba[h];
    }

#pragma unroll
    for (int r = 0; r < 4; r++) {
        int t = t0 + ty * 4 + r;
        float4 v;
        v.x = acc[r][0] + bias[0];
        v.y = acc[r][1] + bias[1];
        v.z = acc[r][2] + bias[2];
        v.w = acc[r][3] + bias[3];
        *(float4*)&U[(size_t)t * (B_DIM * H_DIM) + (size_t)b * H_DIM + h0 + tx * 4] = v;
    }
}

// ---------------------------------------------------------------------------
// Kernel 2: cluster-parallel recurrence. 16 independent clusters of 8 CTAs.
// Cluster c owns batch rows [4c, 4c+4); CTA rank r owns hidden slice
// [64r, 64r+64) with its Waa column slice resident in SMEM (padded rows,
// conflict-free float4 loads). Activations a_t[4][512] are replicated in
// every CTA's SMEM (double-buffered); each step every CTA broadcasts its
// 4x64 fresh outputs to all 8 cluster CTAs via st.shared::cluster, then one
// cluster barrier. No global activation traffic, no global sync.
// ---------------------------------------------------------------------------
#define WROW 516            // padded W row stride in floats (129 float4, %8==1)

__device__ __forceinline__ void st_cluster_f32(uint32_t saddr, int rank, float v)
{
    uint32_t ra;
    asm volatile("mapa.shared::cluster.u32 %0, %1, %2;"
                 : "=r"(ra) : "r"(saddr), "r"(rank));
    asm volatile("st.shared::cluster.f32 [%0], %1;"
                 :: "r"(ra), "f"(v) : "memory");
}

__global__ void __launch_bounds__(256, 1) __cluster_dims__(8, 1, 1)
recurrence_kernel(const float* __restrict__ Waa, float* __restrict__ A)
{
    extern __shared__ float sm[];
    float* Wsh = sm;                     // [64][WROW]          132,096 B
    float* ab  = Wsh + 64 * WROW;        // [2][4][512]          16,384 B
    float* Red = ab + 2 * 4 * H_DIM;     // [4 ks][4 b][64 hh]    4,096 B

    const int tid = threadIdx.x;
    uint32_t rank;
    asm("mov.u32 %0, %%cluster_ctarank;" : "=r"(rank));
    const int cl = blockIdx.x >> 3;      // cluster id 0..15
    const int b0 = cl * 4;               // batch base
    const int n0 = (int)rank * 64;       // hidden slice base

    // Resident Waa slice, transposed: Wsh[hh][k] = Waa[k][n0+hh]
    for (int idx = tid; idx < 64 * H_DIM; idx += 256) {
        int w_h = idx & 63;
        int w_k = idx >> 6;
        Wsh[w_h * WROW + w_k] = Waa[(size_t)w_k * H_DIM + n0 + w_h];
    }
    // Zero a-buffer 0 (a_0 = 0); buffer 1 is written before it is read.
    for (int i = tid; i < 4 * H_DIM; i += 256) ab[i] = 0.0f;
    __syncthreads();   // local-only init; clusters are independent

    const int hh = tid & 63;             // compute: hidden index within slice
    const int ks = tid >> 6;             // compute: K-split 0..3 (128 k each)
    const int eb = tid >> 6;             // epilogue: batch 0..3
    const int eh = tid & 63;             // epilogue: hidden within slice

    const float4* Wp = (const float4*)(Wsh + hh * WROW + ks * 128);

    for (int t = 0; t < T_DIM; t++) {
        const float* Ab = ab + (t & 1) * (4 * H_DIM);
        float*       An = ab + ((t + 1) & 1) * (4 * H_DIM);

        // Prefetch this thread's U value (d_out currently holds U[t]).
        const size_t off = (size_t)t * (B_DIM * H_DIM)
                         + (size_t)(b0 + eb) * H_DIM + n0 + eh;
        const float u = A[off];

        // Partial dot products: 4 batch rows x 1 hidden col, K in [128ks, 128ks+128)
        const float4* A0 = (const float4*)(Ab + 0 * H_DIM + ks * 128);
        const float4* A1 = (const float4*)(Ab + 1 * H_DIM + ks * 128);
        const float4* A2 = (const float4*)(Ab + 2 * H_DIM + ks * 128);
        const float4* A3 = (const float4*)(Ab + 3 * H_DIM + ks * 128);

        float acc0 = 0.f, acc1 = 0.f, acc2 = 0.f, acc3 = 0.f;
#pragma unroll 8
        for (int i = 0; i < 32; i++) {
            float4 wv = Wp[i];
            float4 v0 = A0[i];
            acc0 += v0.x * wv.x + v0.y * wv.y + v0.z * wv.z + v0.w * wv.w;
            float4 v1 = A1[i];
            acc1 += v1.x * wv.x + v1.y * wv.y + v1.z * wv.z + v1.w * wv.w;
            float4 v2 = A2[i];
            acc2 += v2.x * wv.x + v2.y * wv.y + v2.z * wv.z + v2.w * wv.w;
            float4 v3 = A3[i];
            acc3 += v3.x * wv.x + v3.y * wv.y + v3.z * wv.z + v3.w * wv.w;
        }

        Red[(ks * 4 + 0) * 64 + hh] = acc0;
        Red[(ks * 4 + 1) * 64 + hh] = acc1;
        Red[(ks * 4 + 2) * 64 + hh] = acc2;
        Red[(ks * 4 + 3) * 64 + hh] = acc3;
        __syncthreads();

        const int ri = eb * 64 + eh;
        float s = Red[ri] + Red[ri + 256] + Red[ri + 512] + Red[ri + 768];
        float val = tanhf(u + s);

        // Broadcast to every cluster CTA's next-buffer (incl. self).
        uint32_t la = (uint32_t)__cvta_generic_to_shared(&An[eb * H_DIM + n0 + eh]);
#pragma unroll
        for (int r = 0; r < 8; r++) st_cluster_f32(la, r, val);

        // Release our DSMEM writes, overlap the global store with peers' wait.
        asm volatile("barrier.cluster.arrive.aligned;" ::: "memory");
        A[off] = val;
        asm volatile("barrier.cluster.wait.aligned;" ::: "memory");
    }
}

// ---------------------------------------------------------------------------
extern "C" void kernel_launch(void* const* d_in, const int* in_sizes, int n_in,
                              void* d_out, int out_size)
{
    const float* X   = (const float*)d_in[0];
    const float* Wax = (const float*)d_in[1];
    const float* Waa = (const float*)d_in[2];
    const float* bx  = (const float*)d_in[3];
    const float* ba  = (const float*)d_in[4];
    float* out = (float*)d_out;

    const int smem_bytes = (64 * WROW + 2 * 4 * H_DIM + 4 * 4 * 64) * 4; // 152,576
    cudaFuncSetAttribute(recurrence_kernel,
                         cudaFuncAttributeMaxDynamicSharedMemorySize, smem_bytes);

    dim3 g1(H_DIM / 64, T_DIM / 64, B_DIM);   // (8, 8, 64)
    precompute_kernel<<<g1, 256>>>(X, Wax, bx, ba, out);
    recurrence_kernel<<<128, 256, smem_bytes>>>(Waa, out);
}

// round 3
// speedup vs baseline: 1.3214x; 1.2840x over previous
#include <cuda_runtime.h>
#include <cuda_bf16.h>
#include <cstdint>

#define B_DIM 64
#define H_DIM 512
#define I_DIM 512
#define T_DIM 512

// ---------------------------------------------------------------------------
// Kernel 1: U[t,b,h] = sum_i X[b,i,t]*Wax[i,h] + bx[h] + ba[h]  (unchanged)
// ---------------------------------------------------------------------------
__global__ void __launch_bounds__(256)
precompute_kernel(const float* __restrict__ X,
                  const float* __restrict__ Wax,
                  const float* __restrict__ bx,
                  const float* __restrict__ ba,
                  float* __restrict__ U)
{
    __shared__ float As[16][64];
    __shared__ float Bs[16][64];

    const int b  = blockIdx.z;
    const int t0 = blockIdx.y * 64;
    const int h0 = blockIdx.x * 64;
    const int tid = threadIdx.x;
    const int tx = tid & 15;
    const int ty = tid >> 4;

    const float* Xb = X + (size_t)b * I_DIM * T_DIM;

    float acc[4][4];
#pragma unroll
    for (int r = 0; r < 4; r++)
#pragma unroll
        for (int c = 0; c < 4; c++) acc[r][c] = 0.0f;

    const int lr = tid >> 4;
    const int lq = tid & 15;

    for (int i0 = 0; i0 < I_DIM; i0 += 16) {
        const float4* srcA = (const float4*)(Xb + (size_t)(i0 + lr) * T_DIM + t0);
        const float4* srcB = (const float4*)(Wax + (size_t)(i0 + lr) * H_DIM + h0);
        ((float4*)&As[lr][0])[lq] = srcA[lq];
        ((float4*)&Bs[lr][0])[lq] = srcB[lq];
        __syncthreads();
#pragma unroll
        for (int kk = 0; kk < 16; kk++) {
            float4 av = *(const float4*)&As[kk][ty * 4];
            float4 bv = *(const float4*)&Bs[kk][tx * 4];
            acc[0][0] += av.x * bv.x; acc[0][1] += av.x * bv.y;
            acc[0][2] += av.x * bv.z; acc[0][3] += av.x * bv.w;
            acc[1][0] += av.y * bv.x; acc[1][1] += av.y * bv.y;
            acc[1][2] += av.y * bv.z; acc[1][3] += av.y * bv.w;
            acc[2][0] += av.z * bv.x; acc[2][1] += av.z * bv.y;
            acc[2][2] += av.z * bv.z; acc[2][3] += av.z * bv.w;
            acc[3][0] += av.w * bv.x; acc[3][1] += av.w * bv.y;
            acc[3][2] += av.w * bv.z; acc[3][3] += av.w * bv.w;
        }
        __syncthreads();
    }

    float bias[4];
#pragma unroll
    for (int c = 0; c < 4; c++) {
        int h = h0 + tx * 4 + c;
        bias[c] = bx[h] + ba[h];
    }

#pragma unroll
    for (int r = 0; r < 4; r++) {
        int t = t0 + ty * 4 + r;
        float4 v;
        v.x = acc[r][0] + bias[0];
        v.y = acc[r][1] + bias[1];
        v.z = acc[r][2] + bias[2];
        v.w = acc[r][3] + bias[3];
        *(float4*)&U[(size_t)t * (B_DIM * H_DIM) + (size_t)b * H_DIM + h0 + tx * 4] = v;
    }
}

// ---------------------------------------------------------------------------
// Kernel 2: cluster recurrence, W-in-registers edition.
// 16 clusters x 8 CTAs; cluster owns 4 batch rows; CTA rank r owns hidden
// cols [64r,64r+64). 512 threads: thread (ks,hh) holds Waa[64ks..64ks+64)
// [n0+hh] in 16 float4 registers. Activations live in SMEM, triple-buffered,
// layout [buf][rank][b][64]; per-step exchange = 7x 1KB cp.async.bulk DSMEM
// copies landing on each peer's mbarrier (expect_tx 7168). No barrier.cluster
// in the loop, no per-step shared W traffic.
// ---------------------------------------------------------------------------
__global__ void __launch_bounds__(512, 1) __cluster_dims__(8, 1, 1)
recurrence_kernel(const float* __restrict__ Waa, float* __restrict__ A)
{
    extern __shared__ float sm[];
    // sm[0..3]: mbarrier (8B used, 16B reserved)
    float* ab  = sm + 4;            // [3][8][4][64] = 6144 floats
    float* Red = ab + 3 * 2048;     // [8 ks][64 hh][4 b] = 2048 floats

    const int tid = threadIdx.x;
    uint32_t rank;
    asm("mov.u32 %0, %%cluster_ctarank;" : "=r"(rank));
    const int cl = blockIdx.x >> 3;
    const int b0 = cl * 4;
    const int n0 = (int)rank * 64;
    const int ks = tid >> 6;          // 0..7   (warp-uniform: 2 warps per ks)
    const int hh = tid & 63;
    const int k0 = ks * 64;

    const uint32_t mbar = (uint32_t)__cvta_generic_to_shared(sm);

    // One-time: gather this thread's Waa strip into registers (coalesced).
    float4 wreg[16];
#pragma unroll
    for (int i = 0; i < 16; i++) {
        const float* wp = Waa + (size_t)(k0 + 4 * i) * H_DIM + n0 + hh;
        wreg[i].x = wp[0 * H_DIM];
        wreg[i].y = wp[1 * H_DIM];
        wreg[i].z = wp[2 * H_DIM];
        wreg[i].w = wp[3 * H_DIM];
    }

    if (tid == 0) {
        asm volatile("mbarrier.init.shared.b64 [%0], 1;" :: "r"(mbar) : "memory");
    }
    // a_0 = 0 in buffer 0
    for (int i = tid; i < 2048; i += 512) ab[i] = 0.0f;
    __syncthreads();
    asm volatile("barrier.cluster.arrive.aligned;" ::: "memory");
    asm volatile("barrier.cluster.wait.aligned;" ::: "memory");

    const int eb = (tid >> 6) & 3;      // epilogue batch (tid<256)
    const int eh = tid & 63;            // epilogue hidden-within-slice
    const size_t ebase = (size_t)(b0 + eb) * H_DIM + n0 + eh;

    for (int t = 0; t < T_DIM; t++) {
        float* Acur = ab + (t % 3) * 2048;
        float* Anxt = ab + ((t + 1) % 3) * 2048;

        // Prefetch U (d_out currently holds U[t] at this element).
        float u = 0.0f;
        if (tid < 256) u = A[(size_t)t * (B_DIM * H_DIM) + ebase];

        // Wait for a_t (phase t-1), then immediately post expectation for the
        // next exchange (causally before any peer can send phase-t traffic).
        if (t > 0) {
            uint32_t parity = (t - 1) & 1;
            uint32_t done;
            asm volatile(
                "{\n\t.reg .pred p;\n\t"
                "mbarrier.try_wait.parity.acquire.cta.shared::cta.b64 p, [%1], %2;\n\t"
                "selp.b32 %0, 1, 0, p;\n\t}"
                : "=r"(done) : "r"(mbar), "r"(parity) : "memory");
            if (!done) {
                asm volatile(
                    "{\n\t.reg .pred P1;\n\t"
                    "W_%=:\n\t"
                    "mbarrier.try_wait.parity.acquire.cta.shared::cta.b64 P1, [%0], %1, 0x989680;\n\t"
                    "@P1 bra.uni D_%=;\n\t"
                    "bra.uni W_%=;\n\t"
                    "D_%=:\n\t}"
                    :: "r"(mbar), "r"(parity) : "memory");
            }
        }
        if (t < T_DIM - 1 && tid == 0) {
            asm volatile("mbarrier.arrive.expect_tx.shared.b64 _, [%0], %1;"
                         :: "r"(mbar), "r"(7168u) : "memory");
        }

        // Compute: 4 batch-row dot-product partials over K strip [k0,k0+64).
        const float4* Ac4 = (const float4*)Acur + ks * 64;   // [b][16] float4
        float acc0 = 0.f, acc1 = 0.f, acc2 = 0.f, acc3 = 0.f;
#pragma unroll
        for (int i = 0; i < 16; i++) {
            const float4 wv = wreg[i];
            float4 v0 = Ac4[i];
            acc0 += v0.x * wv.x + v0.y * wv.y + v0.z * wv.z + v0.w * wv.w;
            float4 v1 = Ac4[16 + i];
            acc1 += v1.x * wv.x + v1.y * wv.y + v1.z * wv.z + v1.w * wv.w;
            float4 v2 = Ac4[32 + i];
            acc2 += v2.x * wv.x + v2.y * wv.y + v2.z * wv.z + v2.w * wv.w;
            float4 v3 = Ac4[48 + i];
            acc3 += v3.x * wv.x + v3.y * wv.y + v3.z * wv.z + v3.w * wv.w;
        }
        ((float4*)Red)[ks * 64 + hh] = make_float4(acc0, acc1, acc2, acc3);
        __syncthreads();

        if (tid < 256) {
            float s = 0.0f;
#pragma unroll
            for (int w8 = 0; w8 < 8; w8++)
                s += Red[w8 * 256 + eh * 4 + eb];
            float val = tanhf(u + s);
            A[(size_t)t * (B_DIM * H_DIM) + ebase] = val;
            Anxt[(int)rank * 256 + eb * 64 + eh] = val;   // own block, local
        }
        __syncthreads();

        // Ship own 1KB block to the 7 peers (async, lands on their mbarrier).
        if (t < T_DIM - 1 && tid == 0) {
            asm volatile("fence.proxy.async.shared::cta;" ::: "memory");
            uint32_t src = (uint32_t)__cvta_generic_to_shared(Anxt) + rank * 1024u;
#pragma unroll
            for (int r = 0; r < 8; r++) {
                if (r == (int)rank) continue;
                asm volatile(
                    "{\n\t.reg .b32 d, m;\n\t"
                    "mapa.shared::cluster.u32 d, %0, %2;\n\t"
                    "mapa.shared::cluster.u32 m, %1, %2;\n\t"
                    "cp.async.bulk.shared::cluster.shared::cta.mbarrier::complete_tx::bytes "
                    "[d], [%3], 1024, [m];\n\t}"
                    :: "r"(src), "r"(mbar), "r"(r), "r"(src) : "memory");
            }
        }
    }
}

// ---------------------------------------------------------------------------
extern "C" void kernel_launch(void* const* d_in, const int* in_sizes, int n_in,
                              void* d_out, int out_size)
{
    const float* X   = (const float*)d_in[0];
    const float* Wax = (const float*)d_in[1];
    const float* Waa = (const float*)d_in[2];
    const float* bx  = (const float*)d_in[3];
    const float* ba  = (const float*)d_in[4];
    float* out = (float*)d_out;

    // Actual use ~33KB; request 140KB to pin occupancy at 1 CTA/SM so the
    // 128 CTAs land on 128 distinct SMs.
    const int smem_bytes = 140 * 1024;
    cudaFuncSetAttribute(recurrence_kernel,
                         cudaFuncAttributeMaxDynamicSharedMemorySize, smem_bytes);

    dim3 g1(H_DIM / 64, T_DIM / 64, B_DIM);   // (8, 8, 64)
    precompute_kernel<<<g1, 256>>>(X, Wax, bx, ba, out);
    recurrence_kernel<<<128, 512, smem_bytes>>>(Waa, out);
}

// round 5
// speedup vs baseline: 1.5146x; 1.1462x over previous
#include <cuda_runtime.h>
#include <cuda_bf16.h>
#include <cstdint>

#define B_DIM 64
#define H_DIM 512
#define I_DIM 512
#define T_DIM 512

// ---------------------------------------------------------------------------
// Kernel 1: U[t,b,h] = sum_i X[b,i,t]*Wax[i,h] + bx[h] + ba[h]  (unchanged)
// ---------------------------------------------------------------------------
__global__ void __launch_bounds__(256)
precompute_kernel(const float* __restrict__ X,
                  const float* __restrict__ Wax,
                  const float* __restrict__ bx,
                  const float* __restrict__ ba,
                  float* __restrict__ U)
{
    __shared__ float As[16][64];
    __shared__ float Bs[16][64];

    const int b  = blockIdx.z;
    const int t0 = blockIdx.y * 64;
    const int h0 = blockIdx.x * 64;
    const int tid = threadIdx.x;
    const int tx = tid & 15;
    const int ty = tid >> 4;

    const float* Xb = X + (size_t)b * I_DIM * T_DIM;

    float acc[4][4];
#pragma unroll
    for (int r = 0; r < 4; r++)
#pragma unroll
        for (int c = 0; c < 4; c++) acc[r][c] = 0.0f;

    const int lr = tid >> 4;
    const int lq = tid & 15;

    for (int i0 = 0; i0 < I_DIM; i0 += 16) {
        const float4* srcA = (const float4*)(Xb + (size_t)(i0 + lr) * T_DIM + t0);
        const float4* srcB = (const float4*)(Wax + (size_t)(i0 + lr) * H_DIM + h0);
        ((float4*)&As[lr][0])[lq] = srcA[lq];
        ((float4*)&Bs[lr][0])[lq] = srcB[lq];
        __syncthreads();
#pragma unroll
        for (int kk = 0; kk < 16; kk++) {
            float4 av = *(const float4*)&As[kk][ty * 4];
            float4 bv = *(const float4*)&Bs[kk][tx * 4];
            acc[0][0] += av.x * bv.x; acc[0][1] += av.x * bv.y;
            acc[0][2] += av.x * bv.z; acc[0][3] += av.x * bv.w;
            acc[1][0] += av.y * bv.x; acc[1][1] += av.y * bv.y;
            acc[1][2] += av.y * bv.z; acc[1][3] += av.y * bv.w;
            acc[2][0] += av.z * bv.x; acc[2][1] += av.z * bv.y;
            acc[2][2] += av.z * bv.z; acc[2][3] += av.z * bv.w;
            acc[3][0] += av.w * bv.x; acc[3][1] += av.w * bv.y;
            acc[3][2] += av.w * bv.z; acc[3][3] += av.w * bv.w;
        }
        __syncthreads();
    }

    float bias[4];
#pragma unroll
    for (int c = 0; c < 4; c++) {
        int h = h0 + tx * 4 + c;
        bias[c] = bx[h] + ba[h];
    }

#pragma unroll
    for (int r = 0; r < 4; r++) {
        int t = t0 + ty * 4 + r;
        float4 v;
        v.x = acc[r][0] + bias[0];
        v.y = acc[r][1] + bias[1];
        v.z = acc[r][2] + bias[2];
        v.w = acc[r][3] + bias[3];
        *(float4*)&U[(size_t)t * (B_DIM * H_DIM) + (size_t)b * H_DIM + h0 + tx * 4] = v;
    }
}

// ---------------------------------------------------------------------------
// f32x2 helpers
// ---------------------------------------------------------------------------
__device__ __forceinline__ uint64_t pack2(float lo, float hi)
{
    uint64_t r;
    asm("mov.b64 %0, {%1, %2};" : "=l"(r)
        : "r"(__float_as_uint(lo)), "r"(__float_as_uint(hi)));
    return r;
}
__device__ __forceinline__ uint64_t fma2(uint64_t a, uint64_t b, uint64_t c)
{
    uint64_t d;
    asm("fma.rn.f32x2 %0, %1, %2, %3;" : "=l"(d) : "l"(a), "l"(b), "l"(c));
    return d;
}
__device__ __forceinline__ uint64_t add2(uint64_t a, uint64_t b)
{
    uint64_t d;
    asm("add.rn.f32x2 %0, %1, %2;" : "=l"(d) : "l"(a), "l"(b));
    return d;
}
__device__ __forceinline__ void unpack2(uint64_t v, float& lo, float& hi)
{
    uint32_t l, h;
    asm("mov.b64 {%0, %1}, %2;" : "=r"(l), "=r"(h) : "l"(v));
    lo = __uint_as_float(l); hi = __uint_as_float(h);
}

// tanh = 1 - 2/(e^{2x}+1) via ex2/rcp approx (~1e-6 rel err, saturates).
__device__ __forceinline__ float ftanh(float x)
{
    float e;
    asm("ex2.approx.f32 %0, %1;" : "=f"(e) : "f"(x * 2.885390081777927f));
    float r;
    asm("rcp.approx.f32 %0, %1;" : "=f"(r) : "f"(e + 1.0f));
    return fmaf(-2.0f, r, 1.0f);
}

__device__ __forceinline__ void mbar_wait(uint32_t mbar, uint32_t parity)
{
    uint32_t done;
    asm volatile(
        "{\n\t.reg .pred p;\n\t"
        "mbarrier.try_wait.parity.acquire.cta.shared::cta.b64 p, [%1], %2;\n\t"
        "selp.b32 %0, 1, 0, p;\n\t}"
        : "=r"(done) : "r"(mbar), "r"(parity) : "memory");
    if (!done) {
        asm volatile(
            "{\n\t.reg .pred P1;\n\t"
            "W_%=:\n\t"
            "mbarrier.try_wait.parity.acquire.cta.shared::cta.b64 P1, [%0], %1, 0x989680;\n\t"
            "@P1 bra.uni D_%=;\n\t"
            "bra.uni W_%=;\n\t"
            "D_%=:\n\t}"
            :: "r"(mbar), "r"(parity) : "memory");
    }
}

// ---------------------------------------------------------------------------
// Kernel 2: cluster recurrence. 16 clusters x 8 CTAs; cluster owns 4 batch
// rows; CTA rank owns hidden cols [64r,64r+64); Waa strip in registers.
// Exchange: per (source, parity) mbarriers (16) + cp.async.bulk 1KB DSMEM
// copies (reuse distance 2 => race-free re-arm). FFMA2 compute.
// Activation block layout [rank][k(64)][b(4)]: broadcast LDS.128 feeds FFMA2.
// ---------------------------------------------------------------------------
__global__ void __launch_bounds__(512, 1) __cluster_dims__(8, 1, 1)
recurrence_kernel(const float* __restrict__ Waa, float* __restrict__ A)
{
    extern __shared__ float sm[];
    // sm[0..31]: 16 mbarriers (8B each): bar[src][parity] at src*16+par*8 bytes
    float* ab  = sm + 32;           // [3 buf][8 rank][64 k][4 b] = 6144 floats
    float* Red = ab + 3 * 2048;     // [8 ks][4 b][64 hh] = 2048 floats

    const int tid = threadIdx.x;
    uint32_t rank;
    asm("mov.u32 %0, %%cluster_ctarank;" : "=r"(rank));
    const int cl = blockIdx.x >> 3;
    const int b0 = cl * 4;
    const int n0 = (int)rank * 64;
    const int ks = tid >> 6;                 // strip 0..7 (2 warps each)
    const int hh = tid & 63;
    const int k0 = ks * 64;
    const bool local_strip = (ks == (int)rank);

    const uint32_t mbar0 = (uint32_t)__cvta_generic_to_shared(sm);

    // One-time: Waa strip into registers (coalesced).
    float4 wreg[16];
#pragma unroll
    for (int i = 0; i < 16; i++) {
        const float* wp = Waa + (size_t)(k0 + 4 * i) * H_DIM + n0 + hh;
        wreg[i].x = wp[0 * H_DIM];
        wreg[i].y = wp[1 * H_DIM];
        wreg[i].z = wp[2 * H_DIM];
        wreg[i].w = wp[3 * H_DIM];
    }

    if (tid < 16) {
        asm volatile("mbarrier.init.shared.b64 [%0], 1;"
                     :: "r"(mbar0 + tid * 8) : "memory");
    }
    for (int i = tid; i < 2048; i += 512) ab[i] = 0.0f;   // a_0 = 0 (buf 0)
    __syncthreads();
    // Arm phase 0 of both parity objects for every non-local source.
    if (tid < 16 && (tid >> 1) != (int)rank) {
        asm volatile("mbarrier.arrive.expect_tx.shared.b64 _, [%0], %1;"
                     :: "r"(mbar0 + tid * 8), "r"(1024u) : "memory");
    }
    asm volatile("barrier.cluster.arrive.aligned;" ::: "memory");
    asm volatile("barrier.cluster.wait.aligned;" ::: "memory");

    const int eb = (tid >> 6) & 3;          // epilogue batch (tid<256)
    const int eh = tid & 63;
    const size_t ebase = (size_t)(b0 + eb) * H_DIM + n0 + eh;

    for (int t = 0; t < T_DIM; t++) {
        const int cb = t % 3, nb2 = (t + 1) % 3;
        const float* Acur = ab + cb * 2048;
        float* Anxt = ab + nb2 * 2048;

        // Prefetch U (d_out holds U[t] here) before the wait.
        float u = 0.0f;
        if (tid < 256) u = __ldcs(&A[(size_t)t * (B_DIM * H_DIM) + ebase]);

        if (t > 0 && !local_strip) {
            // Data a_t was sent at step t-1 on object [ks][(t-1)&1]; that
            // object's completion parity is ((t-1)>>1)&1.
            const uint32_t obj = mbar0 + (uint32_t)(ks * 16 + ((t - 1) & 1) * 8);
            mbar_wait(obj, (uint32_t)(((t - 1) >> 1) & 1));
            if ((tid & 63) == 0) {           // re-arm for reuse at step t+1
                asm volatile("mbarrier.arrive.expect_tx.shared.b64 _, [%0], %1;"
                             :: "r"(obj), "r"(1024u) : "memory");
            }
        }

        // Compute: strip block [k][b]; broadcast LDS.128 per k feeds FFMA2.
        const float4* Ac4 = (const float4*)Acur + ks * 64;
        uint64_t s0 = 0, s1 = 0, s2 = 0, s3 = 0;
#pragma unroll
        for (int i = 0; i < 16; i++) {
            const float4 w = wreg[i];
            float4 v;
            uint64_t wp;
            v = Ac4[4 * i + 0]; wp = pack2(w.x, w.x);
            s0 = fma2(pack2(v.x, v.y), wp, s0);
            s1 = fma2(pack2(v.z, v.w), wp, s1);
            v = Ac4[4 * i + 1]; wp = pack2(w.y, w.y);
            s2 = fma2(pack2(v.x, v.y), wp, s2);
            s3 = fma2(pack2(v.z, v.w), wp, s3);
            v = Ac4[4 * i + 2]; wp = pack2(w.z, w.z);
            s0 = fma2(pack2(v.x, v.y), wp, s0);
            s1 = fma2(pack2(v.z, v.w), wp, s1);
            v = Ac4[4 * i + 3]; wp = pack2(w.w, w.w);
            s2 = fma2(pack2(v.x, v.y), wp, s2);
            s3 = fma2(pack2(v.z, v.w), wp, s3);
        }
        uint64_t p01 = add2(s0, s2), p23 = add2(s1, s3);
        float a0, a1, a2, a3;
        unpack2(p01, a0, a1);
        unpack2(p23, a2, a3);
        // Red[ks][b][hh] — conflict-free stores and loads
        Red[ks * 256 +   0 + hh] = a0;
        Red[ks * 256 +  64 + hh] = a1;
        Red[ks * 256 + 128 + hh] = a2;
        Red[ks * 256 + 192 + hh] = a3;
        __syncthreads();

        if (tid < 256) {
            float s = u;
#pragma unroll
            for (int w8 = 0; w8 < 8; w8++)
                s += Red[w8 * 256 + eb * 64 + eh];
            float val = ftanh(s);
            __stcs(&A[(size_t)t * (B_DIM * H_DIM) + ebase], val);
            Anxt[rank * 256 + eh * 4 + eb] = val;          // local [k][b] block
        }
        __syncthreads();   // epilogue stores visible; Red safe to reuse

        // Ship own 1KB block to the 7 peers; lands on their bar[rank][t&1].
        if (t < T_DIM - 1 && tid == 0) {
            asm volatile("fence.proxy.async.shared::cta;" ::: "memory");
            uint32_t src = (uint32_t)__cvta_generic_to_shared(Anxt) + rank * 1024u;
            const uint32_t bslot = (uint32_t)(rank * 16 + (t & 1) * 8);
#pragma unroll
            for (int r = 0; r < 8; r++) {
                if (r == (int)rank) continue;
                asm volatile(
                    "{\n\t.reg .b32 d, m;\n\t"
                    "mapa.shared::cluster.u32 d, %0, %2;\n\t"
                    "mapa.shared::cluster.u32 m, %1, %2;\n\t"
                    "cp.async.bulk.shared::cluster.shared::cta.mbarrier::complete_tx::bytes "
                    "[d], [%3], 1024, [m];\n\t}"
                    :: "r"(src), "r"(mbar0 + bslot), "r"(r), "r"(src) : "memory");
            }
        }
    }

    // Keep cluster alive until all DSMEM traffic has landed.
    asm volatile("barrier.cluster.arrive.aligned;" ::: "memory");
    asm volatile("barrier.cluster.wait.aligned;" ::: "memory");
}

// ---------------------------------------------------------------------------
extern "C" void kernel_launch(void* const* d_in, const int* in_sizes, int n_in,
                              void* d_out, int out_size)
{
    const float* X   = (const float*)d_in[0];
    const float* Wax = (const float*)d_in[1];
    const float* Waa = (const float*)d_in[2];
    const float* bx  = (const float*)d_in[3];
    const float* ba  = (const float*)d_in[4];
    float* out = (float*)d_out;

    // Actual use ~33KB; request 140KB to pin 1 CTA/SM.
    const int smem_bytes = 140 * 1024;
    cudaFuncSetAttribute(recurrence_kernel,
                         cudaFuncAttributeMaxDynamicSharedMemorySize, smem_bytes);

    dim3 g1(H_DIM / 64, T_DIM / 64, B_DIM);   // (8, 8, 64)
    precompute_kernel<<<g1, 256>>>(X, Wax, bx, ba, out);
    recurrence_kernel<<<128, 512, smem_bytes>>>(Waa, out);
}

// round 6
// speedup vs baseline: 1.6233x; 1.0718x over previous
#include <cuda_runtime.h>
#include <cuda_bf16.h>
#include <cstdint>

#define B_DIM 64
#define H_DIM 512
#define I_DIM 512
#define T_DIM 512

// ---------------------------------------------------------------------------
// Kernel 1: U[t,b,h] = sum_i X[b,i,t]*Wax[i,h] + bx[h] + ba[h]  (unchanged)
// ---------------------------------------------------------------------------
__global__ void __launch_bounds__(256)
precompute_kernel(const float* __restrict__ X,
                  const float* __restrict__ Wax,
                  const float* __restrict__ bx,
                  const float* __restrict__ ba,
                  float* __restrict__ U)
{
    __shared__ float As[16][64];
    __shared__ float Bs[16][64];

    const int b  = blockIdx.z;
    const int t0 = blockIdx.y * 64;
    const int h0 = blockIdx.x * 64;
    const int tid = threadIdx.x;
    const int tx = tid & 15;
    const int ty = tid >> 4;

    const float* Xb = X + (size_t)b * I_DIM * T_DIM;

    float acc[4][4];
#pragma unroll
    for (int r = 0; r < 4; r++)
#pragma unroll
        for (int c = 0; c < 4; c++) acc[r][c] = 0.0f;

    const int lr = tid >> 4;
    const int lq = tid & 15;

    for (int i0 = 0; i0 < I_DIM; i0 += 16) {
        const float4* srcA = (const float4*)(Xb + (size_t)(i0 + lr) * T_DIM + t0);
        const float4* srcB = (const float4*)(Wax + (size_t)(i0 + lr) * H_DIM + h0);
        ((float4*)&As[lr][0])[lq] = srcA[lq];
        ((float4*)&Bs[lr][0])[lq] = srcB[lq];
        __syncthreads();
#pragma unroll
        for (int kk = 0; kk < 16; kk++) {
            float4 av = *(const float4*)&As[kk][ty * 4];
            float4 bv = *(const float4*)&Bs[kk][tx * 4];
            acc[0][0] += av.x * bv.x; acc[0][1] += av.x * bv.y;
            acc[0][2] += av.x * bv.z; acc[0][3] += av.x * bv.w;
            acc[1][0] += av.y * bv.x; acc[1][1] += av.y * bv.y;
            acc[1][2] += av.y * bv.z; acc[1][3] += av.y * bv.w;
            acc[2][0] += av.z * bv.x; acc[2][1] += av.z * bv.y;
            acc[2][2] += av.z * bv.z; acc[2][3] += av.z * bv.w;
            acc[3][0] += av.w * bv.x; acc[3][1] += av.w * bv.y;
            acc[3][2] += av.w * bv.z; acc[3][3] += av.w * bv.w;
        }
        __syncthreads();
    }

    float bias[4];
#pragma unroll
    for (int c = 0; c < 4; c++) {
        int h = h0 + tx * 4 + c;
        bias[c] = bx[h] + ba[h];
    }

#pragma unroll
    for (int r = 0; r < 4; r++) {
        int t = t0 + ty * 4 + r;
        float4 v;
        v.x = acc[r][0] + bias[0];
        v.y = acc[r][1] + bias[1];
        v.z = acc[r][2] + bias[2];
        v.w = acc[r][3] + bias[3];
        *(float4*)&U[(size_t)t * (B_DIM * H_DIM) + (size_t)b * H_DIM + h0 + tx * 4] = v;
    }
}

// ---------------------------------------------------------------------------
// f32x2 helpers
// ---------------------------------------------------------------------------
__device__ __forceinline__ uint64_t pack2(float lo, float hi)
{
    uint64_t r;
    asm("mov.b64 %0, {%1, %2};" : "=l"(r)
        : "r"(__float_as_uint(lo)), "r"(__float_as_uint(hi)));
    return r;
}
__device__ __forceinline__ uint64_t fma2(uint64_t a, uint64_t b, uint64_t c)
{
    uint64_t d;
    asm("fma.rn.f32x2 %0, %1, %2, %3;" : "=l"(d) : "l"(a), "l"(b), "l"(c));
    return d;
}
__device__ __forceinline__ void unpack2(uint64_t v, float& lo, float& hi)
{
    uint32_t l, h;
    asm("mov.b64 {%0, %1}, %2;" : "=r"(l), "=r"(h) : "l"(v));
    lo = __uint_as_float(l); hi = __uint_as_float(h);
}

// tanh = 1 - 2/(e^{2x}+1) via ex2/rcp approx (~1e-6 rel err, saturates).
__device__ __forceinline__ float ftanh(float x)
{
    float e;
    asm("ex2.approx.f32 %0, %1;" : "=f"(e) : "f"(x * 2.885390081777927f));
    float r;
    asm("rcp.approx.f32 %0, %1;" : "=f"(r) : "f"(e + 1.0f));
    return fmaf(-2.0f, r, 1.0f);
}

__device__ __forceinline__ void mbar_wait(uint32_t mbar, uint32_t parity)
{
    uint32_t done;
    asm volatile(
        "{\n\t.reg .pred p;\n\t"
        "mbarrier.try_wait.parity.acquire.cta.shared::cta.b64 p, [%1], %2;\n\t"
        "selp.b32 %0, 1, 0, p;\n\t}"
        : "=r"(done) : "r"(mbar), "r"(parity) : "memory");
    if (!done) {
        asm volatile(
            "{\n\t.reg .pred P1;\n\t"
            "W_%=:\n\t"
            "mbarrier.try_wait.parity.acquire.cta.shared::cta.b64 P1, [%0], %1, 0x989680;\n\t"
            "@P1 bra.uni D_%=;\n\t"
            "bra.uni W_%=;\n\t"
            "D_%=:\n\t}"
            :: "r"(mbar), "r"(parity) : "memory");
    }
}

// Paired shared load: one LDS.128 -> two f32x2 operands, no movs.
__device__ __forceinline__ void lds_v2b64(uint32_t addr, uint64_t& p, uint64_t& q)
{
    asm volatile("ld.shared.v2.b64 {%0, %1}, [%2];"
                 : "=l"(p), "=l"(q) : "r"(addr));
}

// ---------------------------------------------------------------------------
// Kernel 2: cluster recurrence. 16 clusters x 8 CTAs; cluster owns 4 batch
// rows; CTA rank owns hidden cols [64r,64r+64); Waa strip pre-packed into
// f32x2 register pairs. Exchange: per (source,parity) mbarriers (16) +
// cp.async.bulk 1KB DSMEM copies (distance-2 reuse; issues spread across
// 7 warps). Activation block layout [rank][b(4)][k(64)]: (k,k+1) pairs are
// contiguous, so ld.shared.v2.b64 feeds FFMA2 directly. 12 inst/iter.
// ---------------------------------------------------------------------------
__global__ void __launch_bounds__(512, 1) __cluster_dims__(8, 1, 1)
recurrence_kernel(const float* __restrict__ Waa, float* __restrict__ A)
{
    extern __shared__ float sm[];
    // sm[0..31]: 16 mbarriers: bar[src][parity] at byte src*16 + par*8
    float* ab  = sm + 32;           // [3 buf][8 rank][4 b][64 k] = 6144 floats
    float* Red = ab + 3 * 2048;     // [8 ks][4 b][64 hh] = 2048 floats

    const int tid = threadIdx.x;
    uint32_t rank;
    asm("mov.u32 %0, %%cluster_ctarank;" : "=r"(rank));
    const int cl = blockIdx.x >> 3;
    const int b0 = cl * 4;
    const int n0 = (int)rank * 64;
    const int ks = tid >> 6;                 // strip 0..7 (2 warps each)
    const int hh = tid & 63;
    const int k0 = ks * 64;
    const bool local_strip = (ks == (int)rank);

    const uint32_t mbar0 = (uint32_t)__cvta_generic_to_shared(sm);
    const uint32_t ab_s  = (uint32_t)__cvta_generic_to_shared(ab);

    // One-time: Waa strip, pre-packed as f32x2 pairs over (k,k+1).
    uint64_t wd[32];
#pragma unroll
    for (int i = 0; i < 16; i++) {
        const float* wp = Waa + (size_t)(k0 + 4 * i) * H_DIM + n0 + hh;
        wd[2 * i]     = pack2(wp[0 * H_DIM], wp[1 * H_DIM]);
        wd[2 * i + 1] = pack2(wp[2 * H_DIM], wp[3 * H_DIM]);
    }

    if (tid < 16) {
        asm volatile("mbarrier.init.shared.b64 [%0], 1;"
                     :: "r"(mbar0 + tid * 8) : "memory");
    }
    for (int i = tid; i < 2048; i += 512) ab[i] = 0.0f;   // a_0 = 0 (buf 0)
    __syncthreads();
    if (tid < 16 && (tid >> 1) != (int)rank) {             // arm phase 0
        asm volatile("mbarrier.arrive.expect_tx.shared.b64 _, [%0], %1;"
                     :: "r"(mbar0 + tid * 8), "r"(1024u) : "memory");
    }
    asm volatile("barrier.cluster.arrive.aligned;" ::: "memory");
    asm volatile("barrier.cluster.wait.aligned;" ::: "memory");

    const int eb = (tid >> 6) & 3;          // epilogue batch (tid<256)
    const int eh = tid & 63;
    const size_t ebase = (size_t)(b0 + eb) * H_DIM + n0 + eh;
    const int wsend = tid >> 5;             // warp id (send distribution)

    for (int t = 0; t < T_DIM; t++) {
        const int cb = t % 3, nb2 = (t + 1) % 3;

        // Prefetch U (d_out holds U[t] here) before the wait.
        float u = 0.0f;
        if (tid < 256) u = __ldcs(&A[(size_t)t * (B_DIM * H_DIM) + ebase]);

        if (t > 0 && !local_strip) {
            const uint32_t obj = mbar0 + (uint32_t)(ks * 16 + ((t - 1) & 1) * 8);
            mbar_wait(obj, (uint32_t)(((t - 1) >> 1) & 1));
            if ((tid & 63) == 0) {           // re-arm for reuse at step t+1
                asm volatile("mbarrier.arrive.expect_tx.shared.b64 _, [%0], %1;"
                             :: "r"(obj), "r"(1024u) : "memory");
            }
        }

        // Compute: strip block [b][k]; ld.shared.v2.b64 feeds FFMA2 directly.
        const uint32_t sbase = ab_s + (uint32_t)cb * 8192u + (uint32_t)ks * 1024u;
        uint64_t a0 = 0, a1 = 0, a2 = 0, a3 = 0;
#pragma unroll
        for (int i = 0; i < 16; i++) {
            uint64_t p, q;
            lds_v2b64(sbase +   0u + i * 16u, p, q);
            a0 = fma2(p, wd[2 * i], a0); a0 = fma2(q, wd[2 * i + 1], a0);
            lds_v2b64(sbase + 256u + i * 16u, p, q);
            a1 = fma2(p, wd[2 * i], a1); a1 = fma2(q, wd[2 * i + 1], a1);
            lds_v2b64(sbase + 512u + i * 16u, p, q);
            a2 = fma2(p, wd[2 * i], a2); a2 = fma2(q, wd[2 * i + 1], a2);
            lds_v2b64(sbase + 768u + i * 16u, p, q);
            a3 = fma2(p, wd[2 * i], a3); a3 = fma2(q, wd[2 * i + 1], a3);
        }
        float l0, h0, l1, h1, l2, h2, l3, h3;
        unpack2(a0, l0, h0); unpack2(a1, l1, h1);
        unpack2(a2, l2, h2); unpack2(a3, l3, h3);
        // Red[ks][b][hh] — conflict-free
        Red[ks * 256 +   0 + hh] = l0 + h0;
        Red[ks * 256 +  64 + hh] = l1 + h1;
        Red[ks * 256 + 128 + hh] = l2 + h2;
        Red[ks * 256 + 192 + hh] = l3 + h3;
        __syncthreads();

        if (tid < 256) {
            float s = u;
#pragma unroll
            for (int w8 = 0; w8 < 8; w8++)
                s += Red[w8 * 256 + eb * 64 + eh];
            float val = ftanh(s);
            __stcs(&A[(size_t)t * (B_DIM * H_DIM) + ebase], val);
            // local block, [b][k] layout
            ab[nb2 * 2048 + (int)rank * 256 + eb * 64 + eh] = val;
        }
        __syncthreads();   // epilogue stores visible before send / next read

        // Ship own 1KB block to the 7 peers (one warp per destination).
        if (t < T_DIM - 1 && wsend < 8 && wsend != (int)rank && (tid & 31) == 0) {
            asm volatile("fence.proxy.async.shared::cta;" ::: "memory");
            uint32_t src = ab_s + (uint32_t)nb2 * 8192u + rank * 1024u;
            const uint32_t bs = mbar0 + (uint32_t)(rank * 16 + (t & 1) * 8);
            asm volatile(
                "{\n\t.reg .b32 d, m;\n\t"
                "mapa.shared::cluster.u32 d, %0, %2;\n\t"
                "mapa.shared::cluster.u32 m, %1, %2;\n\t"
                "cp.async.bulk.shared::cluster.shared::cta.mbarrier::complete_tx::bytes "
                "[d], [%0], 1024, [m];\n\t}"
                :: "r"(src), "r"(bs), "r"(wsend) : "memory");
        }
    }

    // Keep cluster alive until all DSMEM traffic has landed.
    asm volatile("barrier.cluster.arrive.aligned;" ::: "memory");
    asm volatile("barrier.cluster.wait.aligned;" ::: "memory");
}

// ---------------------------------------------------------------------------
extern "C" void kernel_launch(void* const* d_in, const int* in_sizes, int n_in,
                              void* d_out, int out_size)
{
    const float* X   = (const float*)d_in[0];
    const float* Wax = (const float*)d_in[1];
    const float* Waa = (const float*)d_in[2];
    const float* bx  = (const float*)d_in[3];
    const float* ba  = (const float*)d_in[4];
    float* out = (float*)d_out;

    // Actual use ~33KB; request 140KB to pin 1 CTA/SM.
    const int smem_bytes = 140 * 1024;
    cudaFuncSetAttribute(recurrence_kernel,
                         cudaFuncAttributeMaxDynamicSharedMemorySize, smem_bytes);

    dim3 g1(H_DIM / 64, T_DIM / 64, B_DIM);   // (8, 8, 64)
    precompute_kernel<<<g1, 256>>>(X, Wax, bx, ba, out);
    recurrence_kernel<<<128, 512, smem_bytes>>>(Waa, out);
}